// round 3
// baseline (speedup 1.0000x reference)
#include <cuda_runtime.h>
#include <math.h>

#define BN 256
#define LL 8
#define EPSV 1e-3f

__device__ float g_last[BN][64][64];
__device__ float g_cc[BN][100][64];
__device__ float g_d0[BN][64][64];
__device__ float g_fb[BN][2][64][64];
__device__ float g_mstate[BN][LL][2][64];
__device__ float g_states[BN][LL][2][64];
__device__ float g_byp[LL][BN][64][64];
__device__ float g_scal[BN];

__global__ void k_init(const float* __restrict__ x, const float* __restrict__ state){
  int b = blockIdx.x;
  for (int idx = threadIdx.x; idx < 64*80; idx += blockDim.x){
    int p = idx/80, c = idx%80;
    if (c < 64) g_last[b][p][c] = x[b*5120 + idx];
  }
  for (int idx = threadIdx.x; idx < 1024; idx += blockDim.x){
    int cp = idx >> 6, f = idx & 63;
    g_mstate[b][cp>>1][cp&1][f] = state[b*1024 + idx] + x[b*5120 + f*80 + 64 + cp];
  }
}

__device__ __forceinline__ void tap1(const float* __restrict__ W, const float* __restrict__ xb,
                                     int ip, int oc, float4& a){
  #pragma unroll 8
  for (int c = 0; c < 64; c++){
    float4 w = *(const float4*)(W + c*64 + oc);
    float xv = xb[ip*64 + c];
    a.x += xv*w.x; a.y += xv*w.y; a.z += xv*w.z; a.w += xv*w.w;
  }
}

template<int NP>
__device__ __forceinline__ void tapN(const float* __restrict__ W, const float* __restrict__ xb,
                                     const int* ip, int oc, float4* a){
  #pragma unroll 2
  for (int c = 0; c < 64; c++){
    float4 w = *(const float4*)(W + c*64 + oc);
    #pragma unroll
    for (int p = 0; p < NP; p++){
      float xv = xb[ip[p]*64 + c];
      a[p].x += xv*w.x; a[p].y += xv*w.y; a[p].z += xv*w.z; a[p].w += xv*w.w;
    }
  }
}

__global__ void __launch_bounds__(256) k_conv(int layer,
                       const float* __restrict__ w4, const float* __restrict__ w3,
                       const float* __restrict__ w2, const float* __restrict__ w1,
                       const float* __restrict__ cb){
  __shared__ float xs[2][64][64];
  int b0 = blockIdx.x * 2;
  for (int idx = threadIdx.x; idx < 8192; idx += 256){
    int bb = idx >> 12, r = idx & 4095;
    (&xs[bb][0][0])[r] = (&g_last[b0+bb][0][0])[r];
  }
  __syncthreads();
  int lane = threadIdx.x & 31, wid = threadIdx.x >> 5;
  int bsel = lane >> 4, oc = (lane & 15)*4;
  const float* xb = &xs[bsel][0][0];
  int b = b0 + bsel;
  const float* W4 = w4 + (size_t)layer*262144;
  const float* W3 = w3 + (size_t)layer*110592;
  const float* W2 = w2 + (size_t)layer*32768;
  const float* W1 = w1 + (size_t)layer*4096;
  const float* CB = cb + layer*256;

  if (wid <= 4){
    if (wid == 0){
      float4 a = {0,0,0,0};
      for (int t = 0; t < 64; t++) tap1(W4 + t*4096, xb, t, oc, a);
      const float* bp = CB + oc;
      a.x += bp[0]; a.y += bp[1]; a.z += bp[2]; a.w += bp[3];
      *(float4*)&g_cc[b][0][oc] = a;
    } else {
      int po = (wid-1)*2;
      int oz = po>>2, oy = (po>>1)&1;
      float4 ac[2] = {{0,0,0,0},{0,0,0,0}};
      for (int kz=0;kz<3;kz++) for(int ky=0;ky<3;ky++) for(int kx=0;kx<3;kx++){
        int base = ((oz+kz)*4 + oy+ky)*4 + kx;
        int ip[2] = {base, base+1};
        tapN<2>(W3 + ((kz*3+ky)*3+kx)*4096, xb, ip, oc, ac);
      }
      const float* bp = CB + 64 + oc;
      #pragma unroll
      for (int p = 0; p < 2; p++){
        float4 v = ac[p];
        v.x += bp[0]; v.y += bp[1]; v.z += bp[2]; v.w += bp[3];
        *(float4*)&g_cc[b][1+po+p][oc] = v;
      }
    }
    int gs = (wid==0) ? 0 : 2*wid-1;
    int gc = (wid==0 || wid==4) ? 1 : 2;
    for (int g = gs; g < gs+gc; g++){
      float4 ac[8];
      int ip[8];
      #pragma unroll
      for (int p = 0; p < 8; p++){ ac[p] = make_float4(0,0,0,0); ip[p] = g*8+p; }
      tapN<8>(W1, xb, ip, oc, ac);
      const float* bp = CB + 192 + oc;
      #pragma unroll
      for (int p = 0; p < 8; p++){
        float4 v = ac[p];
        v.x += bp[0]; v.y += bp[1]; v.z += bp[2]; v.w += bp[3];
        *(float4*)&g_cc[b][36+g*8+p][oc] = v;
      }
    }
  } else {
    int ozg = wid - 5;
    float4 ac[9];
    #pragma unroll
    for (int p = 0; p < 9; p++) ac[p] = make_float4(0,0,0,0);
    for (int kz=0;kz<2;kz++) for(int ky=0;ky<2;ky++) for(int kx=0;kx<2;kx++){
      int ip[9];
      #pragma unroll
      for (int p = 0; p < 9; p++){ int oy=p/3, ox=p%3; ip[p] = ((ozg+kz)*4 + oy+ky)*4 + ox+kx; }
      tapN<9>(W2 + ((kz*2+ky)*2+kx)*4096, xb, ip, oc, ac);
    }
    const float* bp = CB + 128 + oc;
    #pragma unroll
    for (int p = 0; p < 9; p++){
      float4 v = ac[p];
      v.x += bp[0]; v.y += bp[1]; v.z += bp[2]; v.w += bp[3];
      *(float4*)&g_cc[b][9+ozg*9+p][oc] = v;
    }
  }
}

// s0 = sum(mha_out) collapses o@V and out-proj:
// s0 = sum_hk (sum_s colsum_softmax[s]*v[s,hk]) * rowsumWo[hk] + SEQ*sum(bo)
__global__ void k_mha(int layer, int which,
                      const float* __restrict__ qkv_w, const float* __restrict__ qkv_b,
                      const float* __restrict__ out_w, const float* __restrict__ out_b){
  extern __shared__ float sm[];
  int SEQ = which ? 128 : 100;
  int pad = SEQ + 1;
  int b = blockIdx.x;
  int tid = threadIdx.x;
  float* s_x  = sm;
  float* s_q  = s_x  + SEQ*65;
  float* s_k  = s_q  + SEQ*8;
  float* s_v  = s_k  + SEQ*8;
  float* s_sc = s_v  + SEQ*8;
  float* s_ws = s_sc + SEQ*pad;
  float* s_wv = s_ws + SEQ;
  float* s_red= s_wv + 64;

  if (which == 0){
    for (int idx = tid; idx < 100*64; idx += 256){
      int s = idx >> 6, d = idx & 63;
      s_x[s*65 + d] = g_cc[b][s][d];
    }
  } else {
    for (int idx = tid; idx < 128*64; idx += 256){
      int f = idx & 63, t = (idx >> 6) & 63, dr = idx >> 12;
      s_x[(dr*64 + f)*65 + t] = g_fb[b][dr][t][f];
    }
  }
  if (tid < 64) s_wv[tid] = 0.f;
  __syncthreads();

  const float* QW = qkv_w + (size_t)(layer*2+which)*3*64*64;
  const float* QB = qkv_b + (layer*2+which)*3*64;
  const float scale = 0.3535533905932738f;
  int rid = tid % 24, sg = tid / 24;
  int ty = rid >> 3, kk = rid & 7;

  for (int h = 0; h < 8; h++){
    if (tid < 240){
      float wreg[64];
      const float* wp = QW + ty*4096 + h*8 + kk;
      #pragma unroll
      for (int d = 0; d < 64; d++) wreg[d] = wp[d*64];
      float bq = QB[ty*64 + h*8 + kk];
      float* dst = (ty == 0) ? s_q : (ty == 1) ? s_k : s_v;
      for (int s = sg; s < SEQ; s += 10){
        float acc = bq;
        const float* xr = s_x + s*65;
        #pragma unroll
        for (int d = 0; d < 64; d++) acc += xr[d]*wreg[d];
        dst[s*8 + kk] = acc;
      }
    }
    __syncthreads();
    if (tid < SEQ){
      int qi = tid;
      float q0=s_q[qi*8+0],q1=s_q[qi*8+1],q2=s_q[qi*8+2],q3=s_q[qi*8+3];
      float q4=s_q[qi*8+4],q5=s_q[qi*8+5],q6=s_q[qi*8+6],q7=s_q[qi*8+7];
      float* row = s_sc + qi*pad;
      float mx = -1e30f;
      for (int si = 0; si < SEQ; si++){
        const float* kr = s_k + si*8;
        float a = q0*kr[0]+q1*kr[1]+q2*kr[2]+q3*kr[3]
                + q4*kr[4]+q5*kr[5]+q6*kr[6]+q7*kr[7];
        a *= scale;
        row[si] = a;
        mx = fmaxf(mx, a);
      }
      float sum = 0.f;
      for (int si = 0; si < SEQ; si++){
        float e = __expf(row[si] - mx);
        row[si] = e; sum += e;
      }
      float inv = 1.f/sum;
      for (int si = 0; si < SEQ; si++) row[si] *= inv;
    }
    __syncthreads();
    if (tid < SEQ){
      float acc = 0.f;
      for (int qi = 0; qi < SEQ; qi++) acc += s_sc[qi*pad + tid];
      s_ws[tid] = acc;
    }
    __syncthreads();
    if (tid < 64){
      int k2 = tid & 7, ch = tid >> 3;
      float acc = 0.f;
      for (int s = ch; s < SEQ; s += 8) acc += s_ws[s]*s_v[s*8 + k2];
      s_red[tid] = acc;
    }
    __syncthreads();
    if (tid < 8){
      float acc = 0.f;
      #pragma unroll
      for (int ch = 0; ch < 8; ch++) acc += s_red[ch*8 + tid];
      s_wv[h*8 + tid] = acc;
    }
    __syncthreads();
  }
  const float* OW = out_w + (size_t)(layer*2+which)*64*64;
  const float* OB = out_b + (layer*2+which)*64;
  float part = 0.f;
  if (tid < 64){
    float rw = 0.f;
    for (int d = 0; d < 64; d++) rw += OW[tid*64 + d];
    part = s_wv[tid]*rw;
  } else if (tid < 128){
    part = (float)SEQ * OB[tid - 64];
  }
  s_red[tid] = part;
  __syncthreads();
  for (int off = 128; off > 0; off >>= 1){
    if (tid < off) s_red[tid] += s_red[tid + off];
    __syncthreads();
  }
  if (tid == 0) g_scal[b] = s_red[0];
}

__device__ __forceinline__ void ffln(int b, int layer, int which,
                                     const float* ff_w, const float* an_g, const float* an_b,
                                     const float* resid, float* outbuf, float* cur){
  __shared__ float s_red[256];
  int tid = threadIdx.x;
  const float* W0 = ff_w + (size_t)((layer*2+which)*2 + 0)*4096;
  const float* W1 = W0 + 4096;
  float s0 = g_scal[b];
  float part = 0.f;
  for (int idx = tid; idx < 4096; idx += 256){
    float v = s0*W0[idx];
    part += v > 0.f ? v : 0.f;
  }
  s_red[tid] = part; __syncthreads();
  for (int off = 128; off > 0; off >>= 1){
    if (tid < off) s_red[tid] += s_red[tid + off];
    __syncthreads();
  }
  float s1 = s_red[0];
  int p = tid >> 2, q = tid & 3;
  const float* G = an_g + (layer*2+which)*64;
  const float* Bb = an_b + (layer*2+which)*64;
  float sum = 0.f, sq = 0.f;
  #pragma unroll
  for (int c = 0; c < 16; c++){
    int d = q*16 + c;
    float v = s1*W1[p*64 + d] + resid[p*64 + d];
    cur[c] = v; sum += v; sq += v*v;
  }
  sum += __shfl_xor_sync(~0u, sum, 1); sum += __shfl_xor_sync(~0u, sum, 2);
  sq  += __shfl_xor_sync(~0u, sq , 1); sq  += __shfl_xor_sync(~0u, sq , 2);
  float mean = sum*(1.f/64.f);
  float var  = sq*(1.f/64.f) - mean*mean;
  float inv  = rsqrtf(var + EPSV);
  #pragma unroll
  for (int c = 0; c < 16; c++){
    int d = q*16 + c;
    cur[c] = (cur[c] - mean)*inv*G[d] + Bb[d];
    if (outbuf) outbuf[p*64 + d] = cur[c];
  }
}

__global__ void k_post0(int layer, const float* __restrict__ ff_w,
                        const float* __restrict__ an_g, const float* __restrict__ an_b){
  int b = blockIdx.x;
  float cur[16];
  ffln(b, layer, 0, ff_w, an_g, an_b, &g_last[b][0][0], &g_d0[b][0][0], cur);
}

__global__ void k_gru(int layer, const float* __restrict__ gk,
                      const float* __restrict__ gr, const float* __restrict__ gb){
  extern __shared__ float sm[];
  float* s_d0 = sm;
  float* s_xg = s_d0 + 4096;
  float* s_h  = s_xg + 64*192;
  float* s_hg = s_h + 64;
  int b = blockIdx.x >> 1, dir = blockIdx.x & 1;
  int j = threadIdx.x;
  const float* d0b = &g_d0[b][0][0];
  for (int idx = j; idx < 4096; idx += 192) s_d0[idx] = d0b[idx];
  const float* K = gk + (size_t)(layer*2+dir)*64*192;
  const float* R = gr + (size_t)(layer*2+dir)*64*192;
  float bi = gb[((layer*2+dir)*2 + 0)*192 + j];
  float br = gb[((layer*2+dir)*2 + 1)*192 + j];
  float wr[64];
  #pragma unroll
  for (int f = 0; f < 64; f++) wr[f] = K[f*192 + j];
  if (j < 64) s_h[j] = g_mstate[b][layer][dir][j];
  __syncthreads();
  for (int t = 0; t < 64; t++){
    int tc = dir ? (63 - t) : t;
    float acc = bi;
    #pragma unroll
    for (int f = 0; f < 64; f++) acc += s_d0[f*64 + tc]*wr[f];
    s_xg[t*192 + j] = acc;
  }
  #pragma unroll
  for (int f = 0; f < 64; f++) wr[f] = R[f*192 + j];
  __syncthreads();
  for (int t = 0; t < 64; t++){
    float acc = br;
    #pragma unroll
    for (int f = 0; f < 64; f++) acc += s_h[f]*wr[f];
    s_hg[j] = acc;
    __syncthreads();
    if (j < 64){
      float xz = s_xg[t*192 + j], xr = s_xg[t*192 + 64 + j], xh = s_xg[t*192 + 128 + j];
      float z  = 1.f/(1.f + __expf(-(xz + s_hg[j])));
      float rt = 1.f/(1.f + __expf(-(xr + s_hg[64 + j])));
      float c  = tanhf(xh + rt*s_hg[128 + j]);
      float hn = z*s_h[j] + (1.f - z)*c;
      s_h[j] = hn;
      g_fb[b][dir][t][j] = hn;
    }
    __syncthreads();
  }
  if (j < 64) g_states[b][layer][dir][j] = s_h[j];
}

__global__ void k_post1(int layer, const float* __restrict__ ff_w,
                        const float* __restrict__ an_g, const float* __restrict__ an_b,
                        const float* __restrict__ sgp, const float* __restrict__ sbp,
                        int nskip){
  int b = blockIdx.x;
  int tid = threadIdx.x;
  int p = tid >> 2, q = tid & 3;
  float cur[16];
  ffln(b, layer, 1, ff_w, an_g, an_b, &g_d0[b][0][0], &g_byp[layer][b][0][0], cur);
  for (int ss = 0; ss < nskip; ss++){
    int src = layer - (1 << ss) + 1;
    const float* Gs = sgp + (layer*4 + ss)*64;
    const float* Bs = sbp + (layer*4 + ss)*64;
    float sum2 = 0.f, sq2 = 0.f; float t[16];
    #pragma unroll
    for (int c = 0; c < 16; c++){
      int d = q*16 + c;
      float add = (src == layer) ? cur[c] : g_byp[src][b][p][d];
      float v = cur[c] + add;
      t[c] = v; sum2 += v; sq2 += v*v;
    }
    sum2 += __shfl_xor_sync(~0u, sum2, 1); sum2 += __shfl_xor_sync(~0u, sum2, 2);
    sq2  += __shfl_xor_sync(~0u, sq2 , 1); sq2  += __shfl_xor_sync(~0u, sq2 , 2);
    float m2 = sum2*(1.f/64.f);
    float v2 = sq2*(1.f/64.f) - m2*m2;
    float i2 = rsqrtf(v2 + EPSV);
    #pragma unroll
    for (int c = 0; c < 16; c++){
      int d = q*16 + c;
      cur[c] = (t[c] - m2)*i2*Gs[d] + Bs[d];
    }
  }
  #pragma unroll
  for (int c = 0; c < 16; c++){
    int d = q*16 + c;
    g_last[b][p][d] = cur[c];
  }
}

__global__ void k_final(float* __restrict__ out){
  int b = blockIdx.x;
  float* o1 = out;
  float* o2 = out + (size_t)BN*5120;
  for (int idx = threadIdx.x; idx < 64*80; idx += blockDim.x){
    int p = idx/80, c = idx%80;
    float v;
    if (c < 64) v = g_last[b][p][c];
    else { int cc = c - 64; v = g_states[b][cc>>1][cc&1][p]; }
    o1[b*5120 + idx] = v;
  }
  for (int idx = threadIdx.x; idx < 1024; idx += blockDim.x){
    int cp = idx >> 6, f = idx & 63;
    o2[b*1024 + idx] = g_states[b][cp>>1][cp&1][f];
  }
}

extern "C" void kernel_launch(void* const* d_in, const int* in_sizes, int n_in,
                              void* d_out, int out_size){
  const float* x      = (const float*)d_in[0];
  const float* state  = (const float*)d_in[1];
  const float* conv_w4= (const float*)d_in[2];
  const float* conv_w3= (const float*)d_in[3];
  const float* conv_w2= (const float*)d_in[4];
  const float* conv_w1= (const float*)d_in[5];
  const float* conv_b = (const float*)d_in[6];
  const float* qkv_w  = (const float*)d_in[7];
  const float* qkv_b  = (const float*)d_in[8];
  const float* out_w  = (const float*)d_in[9];
  const float* out_b  = (const float*)d_in[10];
  const float* ff_w   = (const float*)d_in[11];
  const float* an_g   = (const float*)d_in[12];
  const float* an_b   = (const float*)d_in[13];
  const float* gru_k  = (const float*)d_in[14];
  const float* gru_r  = (const float*)d_in[15];
  const float* gru_b  = (const float*)d_in[16];
  const float* skip_g = (const float*)d_in[17];
  const float* skip_b = (const float*)d_in[18];

  int smem_mha = (128*65 + 3*128*8 + 128*129 + 128 + 64 + 256) * 4;
  int smem_gru = (4096 + 64*192 + 64 + 192) * 4;
  static int attr_done = 0;
  if (!attr_done){
    cudaFuncSetAttribute(k_mha, cudaFuncAttributeMaxDynamicSharedMemorySize, smem_mha);
    cudaFuncSetAttribute(k_gru, cudaFuncAttributeMaxDynamicSharedMemorySize, smem_gru);
    attr_done = 1;
  }

  k_init<<<BN, 256>>>(x, state);
  for (int i = 0; i < LL; i++){
    int smem0 = (100*65 + 3*100*8 + 100*101 + 100 + 64 + 256) * 4;
    k_conv<<<BN/2, 256>>>(i, conv_w4, conv_w3, conv_w2, conv_w1, conv_b);
    k_mha<<<BN, 256, smem0>>>(i, 0, qkv_w, qkv_b, out_w, out_b);
    k_post0<<<BN, 256>>>(i, ff_w, an_g, an_b);
    k_gru<<<BN*2, 192, smem_gru>>>(i, gru_k, gru_r, gru_b);
    k_mha<<<BN, 256, smem_mha>>>(i, 1, qkv_w, qkv_b, out_w, out_b);
    int ns = 0;
    for (int j = 1; (i+1) % j == 0; j *= 2) ns++;
    k_post1<<<BN, 256>>>(i, ff_w, an_g, an_b, skip_g, skip_b, ns);
  }
  k_final<<<BN, 256>>>((float*)d_out);
}

// round 4
// speedup vs baseline: 1.1260x; 1.1260x over previous
#include <cuda_runtime.h>
#include <math.h>

#define BN 256
#define LL 8
#define EPSV 1e-3f

__device__ float g_last[BN][64][64];
__device__ float g_cc[BN][100][64];
__device__ float g_d0[BN][64][64];      // [b][f=pos][t=dim]
__device__ float g_d0T[BN][64][64];     // [b][t][f]
__device__ float g_fb[BN][2][64][64];   // [b][dir][t][f]
__device__ float g_mstate[BN][LL][2][64];
__device__ float g_states[BN][LL][2][64];
__device__ float g_byp[LL][BN][64][64];
__device__ float g_xg[2*BN][64][192];   // [b*2+dir][t][gate]

__device__ __forceinline__ unsigned pmask(int tid, int lim){
  int rem = lim - (tid & ~31);
  return rem >= 32 ? 0xFFFFFFFFu : ((1u << rem) - 1u);
}

__global__ void k_init(const float* __restrict__ x, const float* __restrict__ state){
  int b = blockIdx.x;
  for (int idx = threadIdx.x; idx < 64*80; idx += blockDim.x){
    int p = idx/80, c = idx%80;
    if (c < 64) g_last[b][p][c] = x[b*5120 + idx];
  }
  for (int idx = threadIdx.x; idx < 1024; idx += blockDim.x){
    int cp = idx >> 6, f = idx & 63;
    g_mstate[b][cp>>1][cp&1][f] = state[b*1024 + idx] + x[b*5120 + f*80 + 64 + cp];
  }
}

// ---------------- conv ----------------
template<int NP>
__device__ __forceinline__ void tapN(const float* __restrict__ W, const float* __restrict__ xb,
                                     const int* ip, int oc, float4* a){
  #pragma unroll 2
  for (int c4 = 0; c4 < 16; c4++){
    float4 xv[NP];
    #pragma unroll
    for (int p = 0; p < NP; p++) xv[p] = *(const float4*)(xb + ip[p]*64 + c4*4);
    #pragma unroll
    for (int cc = 0; cc < 4; cc++){
      float4 w = *(const float4*)(W + (c4*4+cc)*64 + oc);
      #pragma unroll
      for (int p = 0; p < NP; p++){
        float x1 = (cc==0)?xv[p].x:(cc==1)?xv[p].y:(cc==2)?xv[p].z:xv[p].w;
        a[p].x += x1*w.x; a[p].y += x1*w.y; a[p].z += x1*w.z; a[p].w += x1*w.w;
      }
    }
  }
}

__global__ void __launch_bounds__(256) k_conv(int layer,
                       const float* __restrict__ w4, const float* __restrict__ w3,
                       const float* __restrict__ w2, const float* __restrict__ w1,
                       const float* __restrict__ cb){
  __shared__ float xs[2][64][64];
  int b0 = blockIdx.x * 2;
  for (int idx = threadIdx.x; idx < 8192; idx += 256){
    int bb = idx >> 12, r = idx & 4095;
    (&xs[bb][0][0])[r] = (&g_last[b0+bb][0][0])[r];
  }
  __syncthreads();
  int lane = threadIdx.x & 31, wid = threadIdx.x >> 5;
  int bsel = lane >> 4, oc = (lane & 15)*4;
  const float* xb = &xs[bsel][0][0];
  int b = b0 + bsel;
  const float* W4 = w4 + (size_t)layer*262144;
  const float* W3 = w3 + (size_t)layer*110592;
  const float* W2 = w2 + (size_t)layer*32768;
  const float* W1 = w1 + (size_t)layer*4096;
  const float* CB = cb + layer*256;

  if (wid <= 4){
    if (wid == 0){
      float4 a[1] = {{0,0,0,0}};
      for (int t = 0; t < 64; t++){ int ip[1] = {t}; tapN<1>(W4 + t*4096, xb, ip, oc, a); }
      const float* bp = CB + oc;
      a[0].x += bp[0]; a[0].y += bp[1]; a[0].z += bp[2]; a[0].w += bp[3];
      *(float4*)&g_cc[b][0][oc] = a[0];
    } else {
      int po = (wid-1)*2;
      int oz = po>>2, oy = (po>>1)&1;
      float4 ac[2] = {{0,0,0,0},{0,0,0,0}};
      for (int kz=0;kz<3;kz++) for(int ky=0;ky<3;ky++) for(int kx=0;kx<3;kx++){
        int base = ((oz+kz)*4 + oy+ky)*4 + kx;
        int ip[2] = {base, base+1};
        tapN<2>(W3 + ((kz*3+ky)*3+kx)*4096, xb, ip, oc, ac);
      }
      const float* bp = CB + 64 + oc;
      #pragma unroll
      for (int p = 0; p < 2; p++){
        float4 v = ac[p];
        v.x += bp[0]; v.y += bp[1]; v.z += bp[2]; v.w += bp[3];
        *(float4*)&g_cc[b][1+po+p][oc] = v;
      }
    }
    int gs = (wid==0) ? 0 : 2*wid-1;
    int gc = (wid==0 || wid==4) ? 1 : 2;
    for (int g = gs; g < gs+gc; g++){
      float4 ac[8];
      int ip[8];
      #pragma unroll
      for (int p = 0; p < 8; p++){ ac[p] = make_float4(0,0,0,0); ip[p] = g*8+p; }
      tapN<8>(W1, xb, ip, oc, ac);
      const float* bp = CB + 192 + oc;
      #pragma unroll
      for (int p = 0; p < 8; p++){
        float4 v = ac[p];
        v.x += bp[0]; v.y += bp[1]; v.z += bp[2]; v.w += bp[3];
        *(float4*)&g_cc[b][36+g*8+p][oc] = v;
      }
    }
  } else {
    int ozg = wid - 5;
    float4 ac[9];
    #pragma unroll
    for (int p = 0; p < 9; p++) ac[p] = make_float4(0,0,0,0);
    for (int kz=0;kz<2;kz++) for(int ky=0;ky<2;ky++) for(int kx=0;kx<2;kx++){
      int ip[9];
      #pragma unroll
      for (int p = 0; p < 9; p++){ int oy=p/3, ox=p%3; ip[p] = ((ozg+kz)*4 + oy+ky)*4 + ox+kx; }
      tapN<9>(W2 + ((kz*2+ky)*2+kx)*4096, xb, ip, oc, ac);
    }
    const float* bp = CB + 128 + oc;
    #pragma unroll
    for (int p = 0; p < 9; p++){
      float4 v = ac[p];
      v.x += bp[0]; v.y += bp[1]; v.z += bp[2]; v.w += bp[3];
      *(float4*)&g_cc[b][9+ozg*9+p][oc] = v;
    }
  }
}

// ---------------- fused attention + ff + LN (+skip chain for which=1) ----------------
// sum(mha_out) collapses o@V and out-proj:
// s0 = sum_hk (sum_s colsum_softmax[s]*v[s,hk]) * rowsumWo[hk] + SEQ*sum(bo)
__global__ void __launch_bounds__(256) k_att(int layer, int which, int nskip,
                      const float* __restrict__ qkv_w, const float* __restrict__ qkv_b,
                      const float* __restrict__ out_w, const float* __restrict__ out_b,
                      const float* __restrict__ ff_w,
                      const float* __restrict__ an_g, const float* __restrict__ an_b,
                      const float* __restrict__ sgp, const float* __restrict__ sbp){
  extern __shared__ float sm[];
  int SEQ = which ? 128 : 100;
  int pad = SEQ + 1;
  int hs = SEQ >> 1;
  int b = blockIdx.x;
  int tid = threadIdx.x;
  float* s_x  = sm;                 // SEQ*68
  float* s_q  = s_x  + SEQ*68;
  float* s_k  = s_q  + SEQ*8;
  float* s_v  = s_k  + SEQ*8;
  float* s_sc = s_v  + SEQ*8;       // SEQ*pad
  float* s_ws = s_sc + SEQ*pad;
  float* s_wv = s_ws + SEQ;         // 64
  float* s_red= s_wv + 64;          // 256

  if (which == 0){
    for (int idx = tid; idx < 100*64; idx += 256){
      int s = idx >> 6, d = idx & 63;
      s_x[s*68 + d] = g_cc[b][s][d];
    }
  } else {
    for (int idx = tid; idx < 128*64; idx += 256){
      int f = idx & 63, t = (idx >> 6) & 63, dr = idx >> 12;
      s_x[(dr*64 + f)*68 + t] = g_fb[b][dr][t][f];
    }
  }
  if (tid < 64) s_wv[tid] = 0.f;
  __syncthreads();

  const float* QW = qkv_w + (size_t)(layer*2+which)*3*64*64;
  const float* QB = qkv_b + (layer*2+which)*3*64;
  const float scale = 0.3535533905932738f;
  int rid = tid % 24, sg = tid / 24;
  int ty = rid >> 3, kk = rid & 7;

  for (int h = 0; h < 8; h++){
    if (tid < 240){
      float wreg[64];
      const float* wp = QW + ty*4096 + h*8 + kk;
      #pragma unroll
      for (int d = 0; d < 64; d++) wreg[d] = wp[d*64];
      float bq = QB[ty*64 + h*8 + kk];
      float* dst = (ty == 0) ? s_q : (ty == 1) ? s_k : s_v;
      for (int s = sg; s < SEQ; s += 10){
        const float4* xr = (const float4*)(s_x + s*68);
        float acc = bq;
        #pragma unroll
        for (int i = 0; i < 16; i++){
          float4 xv = xr[i];
          acc += xv.x*wreg[4*i] + xv.y*wreg[4*i+1] + xv.z*wreg[4*i+2] + xv.w*wreg[4*i+3];
        }
        dst[s*8 + kk] = acc;
      }
    }
    __syncthreads();
    // scores + softmax: 2 threads per row
    if (tid < 2*SEQ){
      unsigned msk = pmask(tid, 2*SEQ);
      int r = tid >> 1, hf = tid & 1;
      float4 qa = *(float4*)(s_q + r*8), qb4 = *(float4*)(s_q + r*8 + 4);
      float* row = s_sc + r*pad + hf*hs;
      float mx = -1e30f;
      for (int i = 0; i < hs; i++){
        int si = hf*hs + i;
        float4 k0 = *(float4*)(s_k + si*8), k1 = *(float4*)(s_k + si*8 + 4);
        float a = qa.x*k0.x+qa.y*k0.y+qa.z*k0.z+qa.w*k0.w
                + qb4.x*k1.x+qb4.y*k1.y+qb4.z*k1.z+qb4.w*k1.w;
        a *= scale;
        row[i] = a;
        mx = fmaxf(mx, a);
      }
      mx = fmaxf(mx, __shfl_xor_sync(msk, mx, 1));
      float sum = 0.f;
      for (int i = 0; i < hs; i++){
        float e = __expf(row[i] - mx);
        row[i] = e; sum += e;
      }
      sum += __shfl_xor_sync(msk, sum, 1);
      float inv = 1.f/sum;
      for (int i = 0; i < hs; i++) row[i] *= inv;
    }
    __syncthreads();
    // column sums: 2 threads per column
    if (tid < 2*SEQ){
      unsigned msk = pmask(tid, 2*SEQ);
      int col = tid >> 1, hf = tid & 1;
      float acc = 0.f;
      for (int i = 0; i < hs; i++) acc += s_sc[(hf*hs + i)*pad + col];
      acc += __shfl_xor_sync(msk, acc, 1);
      if (!hf) s_ws[col] = acc;
    }
    __syncthreads();
    if (tid < 64){
      int k2 = tid & 7, ch = tid >> 3;
      float acc = 0.f;
      for (int s = ch; s < SEQ; s += 8) acc += s_ws[s]*s_v[s*8 + k2];
      s_red[tid] = acc;
    }
    __syncthreads();
    if (tid < 8){
      float acc = 0.f;
      #pragma unroll
      for (int ch = 0; ch < 8; ch++) acc += s_red[ch*8 + tid];
      s_wv[h*8 + tid] = acc;
    }
    __syncthreads();
  }
  const float* OW = out_w + (size_t)(layer*2+which)*64*64;
  const float* OB = out_b + (layer*2+which)*64;
  float part = 0.f;
  if (tid < 64){
    float rw = 0.f;
    for (int d = 0; d < 64; d++) rw += OW[tid*64 + d];
    part = s_wv[tid]*rw;
  } else if (tid < 128){
    part = (float)SEQ * OB[tid - 64];
  }
  s_red[tid] = part;
  __syncthreads();
  for (int off = 128; off > 0; off >>= 1){
    if (tid < off) s_red[tid] += s_red[tid + off];
    __syncthreads();
  }
  float s0 = s_red[0];
  __syncthreads();

  // ---- ff + LN epilogue ----
  const float* W0 = ff_w + (size_t)((layer*2+which)*2 + 0)*4096;
  const float* W1 = W0 + 4096;
  part = 0.f;
  for (int idx = tid; idx < 4096; idx += 256){
    float v = s0*W0[idx];
    part += fmaxf(v, 0.f);
  }
  s_red[tid] = part; __syncthreads();
  for (int off = 128; off > 0; off >>= 1){
    if (tid < off) s_red[tid] += s_red[tid + off];
    __syncthreads();
  }
  float s1 = s_red[0];
  int p = tid >> 2, q = tid & 3;
  const float* G = an_g + (layer*2+which)*64;
  const float* Bb = an_b + (layer*2+which)*64;
  const float* resid = which ? &g_d0[b][0][0] : &g_last[b][0][0];
  float cur[16]; float sum = 0.f, sq = 0.f;
  #pragma unroll
  for (int c = 0; c < 16; c++){
    int d = q*16 + c;
    float v = s1*W1[p*64 + d] + resid[p*64 + d];
    cur[c] = v; sum += v; sq += v*v;
  }
  sum += __shfl_xor_sync(~0u, sum, 1); sum += __shfl_xor_sync(~0u, sum, 2);
  sq  += __shfl_xor_sync(~0u, sq , 1); sq  += __shfl_xor_sync(~0u, sq , 2);
  float mean = sum*(1.f/64.f);
  float var  = sq*(1.f/64.f) - mean*mean;
  float inv  = rsqrtf(var + EPSV);
  #pragma unroll
  for (int c = 0; c < 16; c++){
    int d = q*16 + c;
    cur[c] = (cur[c] - mean)*inv*G[d] + Bb[d];
  }
  if (which == 0){
    #pragma unroll
    for (int c = 0; c < 16; c++){
      int d = q*16 + c;
      g_d0[b][p][d] = cur[c];
      g_d0T[b][d][p] = cur[c];
    }
  } else {
    #pragma unroll
    for (int c = 0; c < 16; c++){
      int d = q*16 + c;
      g_byp[layer][b][p][d] = cur[c];
    }
    for (int ss = 0; ss < nskip; ss++){
      int src = layer - (1 << ss) + 1;
      const float* Gs = sgp + (layer*4 + ss)*64;
      const float* Bs = sbp + (layer*4 + ss)*64;
      float sum2 = 0.f, sq2 = 0.f; float t[16];
      #pragma unroll
      for (int c = 0; c < 16; c++){
        int d = q*16 + c;
        float add = (src == layer) ? cur[c] : g_byp[src][b][p][d];
        float v = cur[c] + add;
        t[c] = v; sum2 += v; sq2 += v*v;
      }
      sum2 += __shfl_xor_sync(~0u, sum2, 1); sum2 += __shfl_xor_sync(~0u, sum2, 2);
      sq2  += __shfl_xor_sync(~0u, sq2 , 1); sq2  += __shfl_xor_sync(~0u, sq2 , 2);
      float m2 = sum2*(1.f/64.f);
      float v2 = sq2*(1.f/64.f) - m2*m2;
      float i2 = rsqrtf(v2 + EPSV);
      #pragma unroll
      for (int c = 0; c < 16; c++){
        int d = q*16 + c;
        cur[c] = (t[c] - m2)*i2*Gs[d] + Bs[d];
      }
    }
    #pragma unroll
    for (int c = 0; c < 16; c++){
      int d = q*16 + c;
      g_last[b][p][d] = cur[c];
    }
  }
}

// ---------------- GRU input-gate GEMM: xg[b,dir,t,:] = d0T[tc,:] @ K + bi ----------------
__global__ void __launch_bounds__(192) k_gruX(int layer, const float* __restrict__ gk,
                                              const float* __restrict__ gb){
  __shared__ float s_dT[4096];
  int blk = blockIdx.x, b = blk >> 1, dir = blk & 1;
  int j = threadIdx.x;
  for (int idx = j; idx < 4096; idx += 192) s_dT[idx] = (&g_d0T[b][0][0])[idx];
  const float* K = gk + (size_t)(layer*2+dir)*12288;
  float bi = gb[((layer*2+dir)*2 + 0)*192 + j];
  float wr[64];
  #pragma unroll
  for (int f = 0; f < 64; f++) wr[f] = K[f*192 + j];
  __syncthreads();
  for (int t = 0; t < 64; t++){
    int tc = dir ? (63 - t) : t;
    const float4* xr = (const float4*)(s_dT + tc*64);
    float acc = bi;
    #pragma unroll
    for (int i = 0; i < 16; i++){
      float4 xv = xr[i];
      acc += xv.x*wr[4*i] + xv.y*wr[4*i+1] + xv.z*wr[4*i+2] + xv.w*wr[4*i+3];
    }
    g_xg[blk][t][j] = acc;
  }
}

// ---------------- GRU recurrence ----------------
__global__ void __launch_bounds__(192) k_gruR(int layer, const float* __restrict__ gr,
                                              const float* __restrict__ gb){
  __shared__ float s_h[64];
  __shared__ float s_hg[192];
  int blk = blockIdx.x, b = blk >> 1, dir = blk & 1;
  int j = threadIdx.x;
  const float* R = gr + (size_t)(layer*2+dir)*12288;
  float br = gb[((layer*2+dir)*2 + 1)*192 + j];
  float wr[64];
  #pragma unroll
  for (int f = 0; f < 64; f++) wr[f] = R[f*192 + j];
  const float* XG = &g_xg[blk][0][0];
  float xz = 0.f, xr2 = 0.f, xh = 0.f, nz = 0.f, nr = 0.f, nh = 0.f;
  if (j < 64){
    xz = XG[j]; xr2 = XG[64 + j]; xh = XG[128 + j];
    s_h[j] = g_mstate[b][layer][dir][j];
  }
  __syncthreads();
  for (int t = 0; t < 64; t++){
    if (j < 64 && t < 63){
      nz = XG[(t+1)*192 + j]; nr = XG[(t+1)*192 + 64 + j]; nh = XG[(t+1)*192 + 128 + j];
    }
    const float4* h4 = (const float4*)s_h;
    float acc = br;
    #pragma unroll
    for (int i = 0; i < 16; i++){
      float4 hv = h4[i];
      acc += hv.x*wr[4*i] + hv.y*wr[4*i+1] + hv.z*wr[4*i+2] + hv.w*wr[4*i+3];
    }
    s_hg[j] = acc;
    __syncthreads();
    if (j < 64){
      float z  = 1.f/(1.f + __expf(-(xz  + s_hg[j])));
      float rt = 1.f/(1.f + __expf(-(xr2 + s_hg[64 + j])));
      float c  = tanhf(xh + rt*s_hg[128 + j]);
      float hn = z*s_h[j] + (1.f - z)*c;
      s_h[j] = hn;
      g_fb[b][dir][t][j] = hn;
      xz = nz; xr2 = nr; xh = nh;
    }
    __syncthreads();
  }
  if (j < 64) g_states[b][layer][dir][j] = s_h[j];
}

__global__ void k_final(float* __restrict__ out){
  int b = blockIdx.x;
  float* o1 = out;
  float* o2 = out + (size_t)BN*5120;
  for (int idx = threadIdx.x; idx < 64*80; idx += blockDim.x){
    int p = idx/80, c = idx%80;
    float v;
    if (c < 64) v = g_last[b][p][c];
    else { int cc = c - 64; v = g_states[b][cc>>1][cc&1][p]; }
    o1[b*5120 + idx] = v;
  }
  for (int idx = threadIdx.x; idx < 1024; idx += blockDim.x){
    int cp = idx >> 6, f = idx & 63;
    o2[b*1024 + idx] = g_states[b][cp>>1][cp&1][f];
  }
}

extern "C" void kernel_launch(void* const* d_in, const int* in_sizes, int n_in,
                              void* d_out, int out_size){
  const float* x      = (const float*)d_in[0];
  const float* state  = (const float*)d_in[1];
  const float* conv_w4= (const float*)d_in[2];
  const float* conv_w3= (const float*)d_in[3];
  const float* conv_w2= (const float*)d_in[4];
  const float* conv_w1= (const float*)d_in[5];
  const float* conv_b = (const float*)d_in[6];
  const float* qkv_w  = (const float*)d_in[7];
  const float* qkv_b  = (const float*)d_in[8];
  const float* out_w  = (const float*)d_in[9];
  const float* out_b  = (const float*)d_in[10];
  const float* ff_w   = (const float*)d_in[11];
  const float* an_g   = (const float*)d_in[12];
  const float* an_b   = (const float*)d_in[13];
  const float* gru_k  = (const float*)d_in[14];
  const float* gru_r  = (const float*)d_in[15];
  const float* gru_b  = (const float*)d_in[16];
  const float* skip_g = (const float*)d_in[17];
  const float* skip_b = (const float*)d_in[18];

  int smem0 = (100*68 + 3*100*8 + 100*101 + 100 + 64 + 256) * 4;  // 78880
  int smem1 = (128*68 + 3*128*8 + 128*129 + 128 + 64 + 256) * 4;  // 114944
  static int attr_done = 0;
  if (!attr_done){
    cudaFuncSetAttribute(k_att, cudaFuncAttributeMaxDynamicSharedMemorySize, smem1);
    attr_done = 1;
  }

  k_init<<<BN, 256>>>(x, state);
  for (int i = 0; i < LL; i++){
    int ns = 0;
    for (int j = 1; (i+1) % j == 0; j *= 2) ns++;
    k_conv<<<BN/2, 256>>>(i, conv_w4, conv_w3, conv_w2, conv_w1, conv_b);
    k_att<<<BN, 256, smem0>>>(i, 0, 0, qkv_w, qkv_b, out_w, out_b, ff_w, an_g, an_b, skip_g, skip_b);
    k_gruX<<<BN*2, 192>>>(i, gru_k, gru_b);
    k_gruR<<<BN*2, 192>>>(i, gru_r, gru_b);
    k_att<<<BN, 256, smem1>>>(i, 1, ns, qkv_w, qkv_b, out_w, out_b, ff_w, an_g, an_b, skip_g, skip_b);
  }
  k_final<<<BN, 256>>>((float*)d_out);
}